// round 15
// speedup vs baseline: 5.7655x; 1.0471x over previous
#include <cuda_runtime.h>
#include <cuda_fp16.h>
#include <math.h>
#include <stdint.h>

#define HH   512
#define ZZ   128
#define EE   512
#define DD   1152      // 2H + Z
#define VV   32000
#define BSZ  256
#define NN   128
#define G3D  3456      // 3*D
#define NCAT 4480      // 512 (dt_e) + 512 (dt_s) + 3456 (gh)
#define YC   1024      // E + H

// ---------------- scratch (device globals; no allocation allowed) ----------------
__device__ float g_u_e  [BSZ * NN];
__device__ float g_u_s  [BSZ * NN];
__device__ float g_ctx_e[BSZ * HH];
__device__ float g_ctx_s[BSZ * HH];
__device__ float g_plan [BSZ * 2];
__device__ float g_gx   [BSZ * G3D];
__device__ float g_dtgh [BSZ * NCAT];
__device__ int   g_offE [BSZ];
__device__ int   g_offS [BSZ];
__device__ int   g_rowE [BSZ * NN];
__device__ int   g_rowS [BSZ * NN];
__device__ int   g_mtot [2];

// fp16 operands (16B-aligned for cp.async / ldmatrix)
__device__ __align__(256) __half g_ph_h  [BSZ * DD];
__device__ __align__(256) __half g_ee_h  [BSZ * NN * HH];
__device__ __align__(256) __half g_es_h  [BSZ * NN * HH];
__device__ __align__(256) __half g_w1e_h [HH * HH];
__device__ __align__(256) __half g_w1s_h [HH * HH];
__device__ __align__(256) __half g_wcat_h[NCAT * DD];
__device__ __align__(256) __half g_wc_h  [HH * YC];
__device__ __align__(256) __half g_wih_h [G3D * HH];
__device__ __align__(256) __half g_yc_h  [BSZ * YC];
__device__ __align__(256) __half g_x_h   [BSZ * HH];
__device__ __align__(256) __half g_hn_h  [BSZ * DD];

// ---------------- helpers ----------------
__device__ __forceinline__ uint32_t pack_h2(float a, float b) {
    __half2 t = __floats2half2_rn(a, b);
    return *reinterpret_cast<uint32_t*>(&t);
}

__device__ __forceinline__ void mma16816h(float c[4],
                                          uint32_t a0, uint32_t a1, uint32_t a2, uint32_t a3,
                                          uint32_t b0, uint32_t b1) {
    asm volatile(
        "mma.sync.aligned.m16n8k16.row.col.f32.f16.f16.f32 "
        "{%0,%1,%2,%3}, {%4,%5,%6,%7}, {%8,%9}, {%0,%1,%2,%3};\n"
        : "+f"(c[0]), "+f"(c[1]), "+f"(c[2]), "+f"(c[3])
        : "r"(a0), "r"(a1), "r"(a2), "r"(a3), "r"(b0), "r"(b1));
}

__device__ __forceinline__ void ldsm_x4(uint32_t& r0, uint32_t& r1, uint32_t& r2, uint32_t& r3,
                                        uint32_t addr) {
    asm volatile("ldmatrix.sync.aligned.m8n8.x4.shared.b16 {%0,%1,%2,%3}, [%4];"
                 : "=r"(r0), "=r"(r1), "=r"(r2), "=r"(r3) : "r"(addr));
}
__device__ __forceinline__ void ldsm_x2(uint32_t& r0, uint32_t& r1, uint32_t addr) {
    asm volatile("ldmatrix.sync.aligned.m8n8.x2.shared.b16 {%0,%1}, [%2];"
                 : "=r"(r0), "=r"(r1) : "r"(addr));
}

#define CP16(dst, src) \
    asm volatile("cp.async.cg.shared.global [%0], [%1], 16;" :: "r"(dst), "l"(src))
#define CP_COMMIT() asm volatile("cp.async.commit_group;")
#define CP_WAIT2()  asm volatile("cp.async.wait_group 2;")

#define SMS 40
#define STG (128 * SMS)
#define STGB_H (STG * 2)            // 128-row fp16 array = 10240 bytes
#define STAGE_H (2 * STGB_H)        // A(128) + B(128) per stage = 20480
#define SMEM_H (4 * STAGE_H)        // 4-stage: 81920

// BM=64 fp16 constants
#define A64HB (64 * SMS * 2)        // 5120 bytes
#define S64HB (A64HB + STGB_H)      // 15360 per stage
#define SMEM64H (4 * S64HB)         // 4-stage: 61440

__device__ __forceinline__ uint32_t ldsm_aoff(int l) {
    return (uint32_t)((((l & 7) + ((l >> 3) & 1) * 8) * SMS + (l >> 4) * 8) * 2);
}
__device__ __forceinline__ uint32_t ldsm_boff(int l) {
    return (uint32_t)(((l & 7) * SMS + ((l >> 3) & 1) * 8) * 2);
}

// =================================================================================
// gemm_h64: BM=64 x BN=128 fp16 GEMM, both operands pre-converted.
// 4-stage cp.async pipeline; one barrier per chunk; fill post-barrier (stage c+3
// last read by mma of chunk c-1).  Empty commit groups keep in-flight count at 3.
// =================================================================================
__global__ void __launch_bounds__(256, 2) gemm_h64(
    const __half* __restrict__ A, const __half* __restrict__ B,
    const float* __restrict__ bias,
    float* __restrict__ C, __half* __restrict__ Ch,
    int M, int N, int K)
{
    extern __shared__ __half smh[];

    const int t    = threadIdx.x;
    const int m0   = blockIdx.y * 64;
    const int n0   = blockIdx.x * 128;
    const int lane = t & 31;
    const int wid  = t >> 5;
    const int g    = lane >> 2;
    const int tg   = lane & 3;
    const int wr   = wid & 1;
    const int wc   = wid >> 1;

    const uint32_t smb  = (uint32_t)__cvta_generic_to_shared(smh);
    const uint32_t aoff = ldsm_aoff(lane);
    const uint32_t boff = ldsm_boff(lane);

    const int ar = t >> 2;
    const int ac = (t & 3) * 8;
    const uint32_t atoff = (uint32_t)(ar * SMS + ac) * 2;
    const int br = t >> 1;
    const int bc = (t & 1) * 16;
    const uint32_t btoff = (uint32_t)(br * SMS + bc) * 2;

    const __half* Ap = A + (size_t)(m0 + ar) * K + ac;
    const __half* Bp = B + (size_t)(n0 + br) * K + bc;

    float acc[2][4][4];
#pragma unroll
    for (int mi = 0; mi < 2; mi++)
#pragma unroll
        for (int ni = 0; ni < 4; ni++)
#pragma unroll
            for (int q = 0; q < 4; q++) acc[mi][ni][q] = 0.f;

#define FILLH64(D, K0)                                   \
    do {                                                 \
        CP16((D) + atoff,              Ap + (K0));       \
        CP16((D) + A64HB + btoff,      Bp + (K0));       \
        CP16((D) + A64HB + btoff + 16, Bp + (K0) + 8);   \
    } while (0)

    const int NC = K >> 5;
#pragma unroll
    for (int i = 0; i < 3; i++) {
        if (i < NC) FILLH64(smb + (uint32_t)i * S64HB, i * 32);
        CP_COMMIT();
    }

    for (int c = 0; c < NC; c++) {
        CP_WAIT2();
        __syncthreads();
        if (c + 3 < NC) FILLH64(smb + (uint32_t)((c + 3) & 3) * S64HB, (c + 3) * 32);
        CP_COMMIT();
        const uint32_t stb = smb + (uint32_t)(c & 3) * S64HB;
#pragma unroll
        for (int ks = 0; ks < 2; ks++) {
            const uint32_t kb2 = ks * 32;
            uint32_t bf[4][2];
#pragma unroll
            for (int ni = 0; ni < 4; ni++) {
                const uint32_t rb = (uint32_t)(wc * 32 + ni * 8) * (SMS * 2) + kb2 + boff;
                ldsm_x2(bf[ni][0], bf[ni][1], stb + A64HB + rb);
            }
#pragma unroll
            for (int mi = 0; mi < 2; mi++) {
                const uint32_t ra = (uint32_t)(wr * 32 + mi * 16) * (SMS * 2) + kb2 + aoff;
                uint32_t a0, a1, a2, a3;
                ldsm_x4(a0, a1, a2, a3, stb + ra);
#pragma unroll
                for (int ni = 0; ni < 4; ni++)
                    mma16816h(acc[mi][ni], a0, a1, a2, a3, bf[ni][0], bf[ni][1]);
            }
        }
    }

#pragma unroll
    for (int mi = 0; mi < 2; mi++) {
        const int row = m0 + wr * 32 + mi * 16 + g;
#pragma unroll
        for (int ni = 0; ni < 4; ni++) {
            const int col = n0 + wc * 32 + ni * 8 + tg * 2;
            float b0 = bias ? bias[col] : 0.f;
            float b1 = bias ? bias[col + 1] : 0.f;
            float c00 = acc[mi][ni][0] + b0, c01 = acc[mi][ni][1] + b1;
            float c10 = acc[mi][ni][2] + b0, c11 = acc[mi][ni][3] + b1;
            if (C) {
                *(float2*)&C[(size_t)row * N + col]       = make_float2(c00, c01);
                *(float2*)&C[(size_t)(row + 8) * N + col] = make_float2(c10, c11);
            }
            if (Ch) {
                *(uint32_t*)&Ch[(size_t)row * N + col]       = pack_h2(c00, c01);
                *(uint32_t*)&Ch[(size_t)(row + 8) * N + col] = pack_h2(c10, c11);
            }
        }
    }
}

// =================================================================================
// gemm_fp16: Wout GEMM (BM=128).  A fp16 4-stage cp.async; B fp32 LDG -> fp16
// smem one chunk ahead (written after mma to stage (c+1)&3; iter c+1's barrier
// orders the STS before the read).
// =================================================================================
__global__ void __launch_bounds__(256, 2) gemm_fp16(
    const __half* __restrict__ A, const float* __restrict__ B,
    const float* __restrict__ bias, float* __restrict__ C,
    int M, int N, int K)
{
    extern __shared__ __half smh[];

    const int t    = threadIdx.x;
    const int m0   = blockIdx.y * 128;
    const int n0   = blockIdx.x * 128;
    const int lane = t & 31;
    const int wid  = t >> 5;
    const int g    = lane >> 2;
    const int tg   = lane & 3;
    const int wr   = wid & 1;
    const int wc   = wid >> 1;

    const uint32_t smb  = (uint32_t)__cvta_generic_to_shared(smh);
    const uint32_t aoff = ldsm_aoff(lane);
    const uint32_t boff = ldsm_boff(lane);

    const int r  = t >> 1;
    const int hh = (t & 1) * 16;
    const uint32_t toff = (uint32_t)(r * SMS + hh) * 2;
    const int idx = r * SMS + hh;
    const __half* Ap = A + (size_t)(m0 + r) * K + hh;
    const float*  Bp = B + (size_t)(n0 + r) * K + hh;

    float acc[4][4][4];
#pragma unroll
    for (int mi = 0; mi < 4; mi++)
#pragma unroll
        for (int ni = 0; ni < 4; ni++)
#pragma unroll
            for (int q = 0; q < 4; q++) acc[mi][ni][q] = 0.f;

#define CVTB_H(ST, RB)                                                        \
    do {                                                                      \
        __half* bdst = smh + (ST) * (STAGE_H / 2) + (STGB_H / 2) + idx;       \
        uint4 v0, v1;                                                         \
        v0.x = pack_h2((RB)[0].x, (RB)[0].y); v0.y = pack_h2((RB)[0].z, (RB)[0].w); \
        v0.z = pack_h2((RB)[1].x, (RB)[1].y); v0.w = pack_h2((RB)[1].z, (RB)[1].w); \
        v1.x = pack_h2((RB)[2].x, (RB)[2].y); v1.y = pack_h2((RB)[2].z, (RB)[2].w); \
        v1.z = pack_h2((RB)[3].x, (RB)[3].y); v1.w = pack_h2((RB)[3].z, (RB)[3].w); \
        *(uint4*)bdst       = v0;                                             \
        *(uint4*)(bdst + 8) = v1;                                             \
    } while (0)

    const int NC = K >> 5;

    // B chunk 0 -> stage 0 (visible after iter-0 barrier)
    {
        float4 rb0[4];
#pragma unroll
        for (int i = 0; i < 4; i++) rb0[i] = *(const float4*)(Bp + i * 4);
        CVTB_H(0, rb0);
    }
    // A prologue: stages 0..2
#pragma unroll
    for (int i = 0; i < 3; i++) {
        if (i < NC) {
            const uint32_t d = smb + (uint32_t)i * STAGE_H + toff;
            CP16(d,      Ap + i * 32);
            CP16(d + 16, Ap + i * 32 + 8);
        }
        CP_COMMIT();
    }

    for (int c = 0; c < NC; c++) {
        CP_WAIT2();
        __syncthreads();
        if (c + 3 < NC) {
            const uint32_t d = smb + (uint32_t)((c + 3) & 3) * STAGE_H + toff;
            CP16(d,      Ap + (c + 3) * 32);
            CP16(d + 16, Ap + (c + 3) * 32 + 8);
        }
        CP_COMMIT();
        float4 rb[4];
        const bool moreB = (c + 1 < NC);
        if (moreB) {
#pragma unroll
            for (int i = 0; i < 4; i++) rb[i] = *(const float4*)(Bp + (c + 1) * 32 + i * 4);
        }
        const uint32_t stb = smb + (uint32_t)(c & 3) * STAGE_H;
#pragma unroll
        for (int ks = 0; ks < 2; ks++) {
            const uint32_t kb2 = ks * 32;
            uint32_t bf[4][2];
#pragma unroll
            for (int ni = 0; ni < 4; ni++) {
                const uint32_t rbo = (uint32_t)(wc * 32 + ni * 8) * (SMS * 2) + kb2 + boff;
                ldsm_x2(bf[ni][0], bf[ni][1], stb + STGB_H + rbo);
            }
#pragma unroll
            for (int mi = 0; mi < 4; mi++) {
                const uint32_t ra = (uint32_t)(wr * 64 + mi * 16) * (SMS * 2) + kb2 + aoff;
                uint32_t a0, a1, a2, a3;
                ldsm_x4(a0, a1, a2, a3, stb + ra);
#pragma unroll
                for (int ni = 0; ni < 4; ni++)
                    mma16816h(acc[mi][ni], a0, a1, a2, a3, bf[ni][0], bf[ni][1]);
            }
        }
        if (moreB) CVTB_H((c + 1) & 3, rb);
    }

#pragma unroll
    for (int mi = 0; mi < 4; mi++) {
        const int row = m0 + wr * 64 + mi * 16 + g;
#pragma unroll
        for (int ni = 0; ni < 4; ni++) {
            const int col = n0 + wc * 32 + ni * 8 + tg * 2;
            const float b0 = bias[col], b1 = bias[col + 1];
            *(float2*)&C[(size_t)row * N + col] =
                make_float2(acc[mi][ni][0] + b0, acc[mi][ni][1] + b1);
            *(float2*)&C[(size_t)(row + 8) * N + col] =
                make_float2(acc[mi][ni][2] + b0, acc[mi][ni][3] + b1);
        }
    }
}

// =================================================================================
// cvt_all: batched fp32 -> fp16 conversion (grid.y = segment)
// =================================================================================
struct CvtSeg { const float* src; __half* dst; int n4; };
struct CvtArgs { CvtSeg seg[8]; };

__global__ void cvt_all(CvtArgs a)
{
    const CvtSeg s = a.seg[blockIdx.y];
    const int i = blockIdx.x * blockDim.x + threadIdx.x;
    if (i >= s.n4) return;
    float4 v = ((const float4*)s.src)[i];
    uint2 o;
    o.x = pack_h2(v.x, v.y);
    o.y = pack_h2(v.z, v.w);
    ((uint2*)s.dst)[i] = o;
}

// =================================================================================
// compact: per-batch exclusive offsets of unmasked positions (both masks)
// =================================================================================
__global__ void compact_kernel(const int* __restrict__ mE, const int* __restrict__ mS,
                               int* __restrict__ offE, int* __restrict__ offS,
                               int* __restrict__ mtot)
{
    __shared__ int sE[256], sS[256];
    const int b = threadIdx.x;
    int cE = 0, cS = 0;
    for (int n = 0; n < NN; n++) {
        cE += (mE[b * NN + n] == 0);
        cS += (mS[b * NN + n] == 0);
    }
    sE[b] = cE; sS[b] = cS;
    __syncthreads();
    for (int d = 1; d < 256; d <<= 1) {
        int vE = 0, vS = 0;
        if (b >= d) { vE = sE[b - d]; vS = sS[b - d]; }
        __syncthreads();
        sE[b] += vE; sS[b] += vS;
        __syncthreads();
    }
    offE[b] = sE[b] - cE;
    offS[b] = sS[b] - cS;
    if (b == 255) { mtot[0] = sE[255]; mtot[1] = sS[255]; }
}

// =================================================================================
// merged gather (grid.y = side): compact unmasked enc rows -> fp16
// =================================================================================
__global__ void gather2(const float* __restrict__ encE, const float* __restrict__ encS,
                        const int* __restrict__ mE, const int* __restrict__ mS,
                        const int* __restrict__ offE, const int* __restrict__ offS,
                        __half* __restrict__ geh, __half* __restrict__ gsh,
                        int* __restrict__ rowE, int* __restrict__ rowS,
                        float* __restrict__ uE, float* __restrict__ uS)
{
    const int side = blockIdx.y;
    const float* enc = side ? encS : encE;
    const int* mask  = side ? mS : mE;
    const int* off   = side ? offS : offE;
    __half* gh = side ? gsh : geh;
    int* rowinfo = side ? rowS : rowE;
    float* u     = side ? uS : uE;

    __shared__ int s_list[NN];
    __shared__ int s_wtot[8];
    const int b = blockIdx.x;
    const int t = threadIdx.x;
    const int base = off[b];
    const bool in = t < NN;
    const bool valid = in && (mask[b * NN + t] == 0);
    const unsigned wm = __ballot_sync(0xffffffffu, valid);
    const int lane = t & 31, w = t >> 5;
    if (lane == 0) s_wtot[w] = __popc(wm);
    __syncthreads();
    int wbase = 0;
#pragma unroll
    for (int i = 0; i < 4; i++) if (i < w) wbase += s_wtot[i];
    const int rank = wbase + __popc(wm & ((1u << lane) - 1));
    if (valid) {
        s_list[rank] = t;
        rowinfo[base + rank] = b * NN + t;
    } else if (in) {
        u[b * NN + t] = -INFINITY;
    }
    __syncthreads();
    const int cnt = s_wtot[0] + s_wtot[1] + s_wtot[2] + s_wtot[3];

    for (int i = 0; i < cnt; i++) {
        const int n = s_list[i];
        const float2 v = *(const float2*)(enc + ((size_t)b * NN + n) * HH + t * 2);
        *(uint32_t*)&gh[((size_t)base + i) * HH + t * 2] = pack_h2(v.x, v.y);
    }
}

// =================================================================================
// merged attention, fp16 single-pass, 4-stage pipeline (grid = (256, 2)).
// Barrier at nc start protects stages from the previous n-chunk's trailing mma.
// =================================================================================
__global__ void __launch_bounds__(256, 2) attn2h(
    const __half* __restrict__ geh, const __half* __restrict__ gsh,
    const __half* __restrict__ w1eh, const __half* __restrict__ w1sh,
    const float* __restrict__ dtg,
    const float* __restrict__ vte, const float* __restrict__ vts,
    const int* __restrict__ rowE, const int* __restrict__ rowS,
    const int* __restrict__ mtotp,
    float* __restrict__ uE, float* __restrict__ uS)
{
    extern __shared__ __half smh[];
    __shared__ float s_vt[512];
    __shared__ float s_u[128];

    const int side = blockIdx.y;
    const int mtot = mtotp[side];
    const int m0 = blockIdx.x * 128;
    if (m0 >= mtot) return;

    const __half* ge  = side ? gsh : geh;
    const __half* w1h = side ? w1sh : w1eh;
    const float* vt = side ? vts : vte;
    const int* rowinfo = side ? rowS : rowE;
    float* u = side ? uS : uE;

    const int t    = threadIdx.x;
    const int lane = t & 31;
    const int wid  = t >> 5;
    const int g    = lane >> 2;
    const int tg   = lane & 3;
    const int wr   = wid & 1;
    const int wc   = wid >> 1;

    const uint32_t smb  = (uint32_t)__cvta_generic_to_shared(smh);
    const uint32_t aoff = ldsm_aoff(lane);
    const uint32_t boff = ldsm_boff(lane);

    for (int i = t; i < 512; i += 256) s_vt[i] = vt[i];
    if (t < 128) s_u[t] = 0.f;

    int rb4[4][2];
#pragma unroll
    for (int mi = 0; mi < 4; mi++)
#pragma unroll
        for (int rr = 0; rr < 2; rr++)
            rb4[mi][rr] = rowinfo[m0 + wr * 64 + mi * 16 + g + rr * 8] >> 7;

    const int r  = t >> 1;
    const int hh = (t & 1) * 16;
    const uint32_t toff = (uint32_t)(r * SMS + hh) * 2;
    const __half* Ap = ge + (size_t)(m0 + r) * 512 + hh;

    float up[8];
#pragma unroll
    for (int i = 0; i < 8; i++) up[i] = 0.f;

#define AFILL(ST, K0)                                          \
    do {                                                       \
        const uint32_t d = smb + (uint32_t)(ST) * STAGE_H;     \
        CP16(d + toff,               Ap + (K0));               \
        CP16(d + toff + 16,          Ap + (K0) + 8);           \
        CP16(d + STGB_H + toff,      Bp + (K0));               \
        CP16(d + STGB_H + toff + 16, Bp + (K0) + 8);           \
    } while (0)

    for (int nc = 0; nc < 4; nc++) {
        const __half* Bp = w1h + (size_t)(nc * 128 + r) * 512 + hh;

        float acc[4][4][4];
#pragma unroll
        for (int mi = 0; mi < 4; mi++)
#pragma unroll
            for (int ni = 0; ni < 4; ni++)
#pragma unroll
                for (int q = 0; q < 4; q++) acc[mi][ni][q] = 0.f;

        __syncthreads();   // all warps past previous nc's mma before refilling
#pragma unroll
        for (int i = 0; i < 3; i++) {
            AFILL(i, i * 32);
            CP_COMMIT();
        }

        for (int c = 0; c < 16; c++) {
            CP_WAIT2();
            __syncthreads();
            if (c + 3 < 16) AFILL((c + 3) & 3, (c + 3) * 32);
            CP_COMMIT();
            const uint32_t stb = smb + (uint32_t)(c & 3) * STAGE_H;
#pragma unroll
            for (int ks = 0; ks < 2; ks++) {
                const uint32_t kb2 = ks * 32;
                uint32_t bf[4][2];
#pragma unroll
                for (int ni = 0; ni < 4; ni++) {
                    const uint32_t rbo = (uint32_t)(wc * 32 + ni * 8) * (SMS * 2) + kb2 + boff;
                    ldsm_x2(bf[ni][0], bf[ni][1], stb + STGB_H + rbo);
                }
#pragma unroll
                for (int mi = 0; mi < 4; mi++) {
                    const uint32_t ra = (uint32_t)(wr * 64 + mi * 16) * (SMS * 2) + kb2 + aoff;
                    uint32_t a0, a1, a2, a3;
                    ldsm_x4(a0, a1, a2, a3, stb + ra);
#pragma unroll
                    for (int ni = 0; ni < 4; ni++)
                        mma16816h(acc[mi][ni], a0, a1, a2, a3, bf[ni][0], bf[ni][1]);
                }
            }
        }

#pragma unroll
        for (int mi = 0; mi < 4; mi++) {
            const float* dt0 = dtg + (size_t)rb4[mi][0] * NCAT + (side ? HH : 0);
            const float* dt1 = dtg + (size_t)rb4[mi][1] * NCAT + (side ? HH : 0);
#pragma unroll
            for (int ni = 0; ni < 4; ni++) {
                const int col = nc * 128 + wc * 32 + ni * 8 + tg * 2;
                const float v0 = s_vt[col], v1 = s_vt[col + 1];
                up[mi * 2 + 0] += v0 * tanhf(acc[mi][ni][0] + dt0[col])
                                + v1 * tanhf(acc[mi][ni][1] + dt0[col + 1]);
                up[mi * 2 + 1] += v0 * tanhf(acc[mi][ni][2] + dt1[col])
                                + v1 * tanhf(acc[mi][ni][3] + dt1[col + 1]);
            }
        }
    }

#pragma unroll
    for (int mi = 0; mi < 4; mi++)
#pragma unroll
        for (int rr = 0; rr < 2; rr++) {
            float v = up[mi * 2 + rr];
            v += __shfl_down_sync(0xffffffffu, v, 1);
            v += __shfl_down_sync(0xffffffffu, v, 2);
            if (tg == 0)
                atomicAdd(&s_u[wr * 64 + mi * 16 + g + rr * 8], v);
        }
    __syncthreads();

    if (t < 128 && m0 + t < mtot)
        u[rowinfo[m0 + t]] = s_u[t];
}

// =================================================================================
// plan = softmax(prev_h @ plan_W^T + plan_b)   (256 threads, float4)
// =================================================================================
__global__ void plan_kernel(const float* __restrict__ prev_h,
                            const float* __restrict__ plan_W,
                            const float* __restrict__ plan_b,
                            float* __restrict__ plan,
                            float* __restrict__ out_plan)
{
    const int b = blockIdx.x;
    const int t = threadIdx.x;
    __shared__ float s0[256], s1[256];
    float a0 = 0.f, a1 = 0.f;
    const float4* hb = (const float4*)(prev_h + (size_t)b * DD);
    const float4* w0 = (const float4*)plan_W;
    const float4* w1 = (const float4*)(plan_W + DD);
    for (int k = t; k < DD / 4; k += 256) {
        const float4 h = hb[k], x = w0[k], y = w1[k];
        a0 += h.x * x.x + h.y * x.y + h.z * x.z + h.w * x.w;
        a1 += h.x * y.x + h.y * y.y + h.z * y.z + h.w * y.w;
    }
    s0[t] = a0; s1[t] = a1;
    __syncthreads();
    for (int s = 128; s > 0; s >>= 1) {
        if (t < s) { s0[t] += s0[t + s]; s1[t] += s1[t + s]; }
        __syncthreads();
    }
    if (t == 0) {
        const float l0 = s0[0] + plan_b[0];
        const float l1 = s1[0] + plan_b[1];
        const float mx = fmaxf(l0, l1);
        const float e0 = expf(l0 - mx), e1 = expf(l1 - mx);
        const float inv = 1.f / (e0 + e1);
        plan[2 * b] = e0 * inv;       plan[2 * b + 1] = e1 * inv;
        out_plan[2 * b] = e0 * inv;   out_plan[2 * b + 1] = e1 * inv;
    }
}

// =================================================================================
// merged softmax+context (grid = (BSZ, 2)) — skips masked rows
// =================================================================================
__global__ void softmax_ctx2(const float* __restrict__ uE, const float* __restrict__ uS,
                             const float* __restrict__ encE, const float* __restrict__ encS,
                             float* __restrict__ ctxE, float* __restrict__ ctxS)
{
    const int side = blockIdx.y;
    const float* u   = side ? uS : uE;
    const float* enc = side ? encS : encE;
    float* ctx       = side ? ctxS : ctxE;

    const int b = blockIdx.x;
    const int t = threadIdx.x;
    __shared__ float red[256];
    __shared__ float s_aw[NN];
    __shared__ int   s_list[NN];
    __shared__ int   s_wtot[4];

    const float uv = (t < NN) ? u[(size_t)b * NN + t] : -INFINITY;
    red[t] = uv;
    __syncthreads();
    for (int s = 128; s > 0; s >>= 1) {
        if (t < s) red[t] = fmaxf(red[t], red[t + s]);
        __syncthreads();
    }
    const float mx = red[0];
    __syncthreads();
    const float e = (t < NN) ? expf(uv - mx) : 0.f;
    red[t] = e;
    __syncthreads();
    for (int s = 128; s > 0; s >>= 1) {
        if (t < s) red[t] += red[t + s];
        __syncthreads();
    }
    const float inv = 1.f / red[0];

    const bool valid = (t < NN) && (uv != -INFINITY);
    const unsigned wm = __ballot_sync(0xffffffffu, valid);
    const int lane = t & 31, w = t >> 5;
    if (lane == 0 && w < 4) s_wtot[w] = __popc(wm);
    __syncthreads();
    int wbase = 0;
#pragma unroll
    for (int i = 0; i < 4; i++) if (i < w) wbase += s_wtot[i];
    if (valid) {
        const int rank = wbase + __popc(wm & ((1u << lane) - 1));
        s_list[rank] = t;
        s_aw[rank] = e * inv;
    }
    __syncthreads();
    const int cnt = s_wtot[0] + s_wtot[1] + s_wtot[2] + s_wtot[3];

    const float* eb = enc + (size_t)b * NN * HH;
    for (int h = t; h < HH; h += 256) {
        float s = 0.f;
        for (int i = 0; i < cnt; i++)
            s += s_aw[i] * eb[(size_t)s_list[i] * HH + h];
        ctx[(size_t)b * HH + h] = s;
    }
}

// =================================================================================
// y_ctx = [prev_y | plan0*ctx_e + plan1*ctx_s], written fp16
// =================================================================================
__global__ void combine_kernel(const float* __restrict__ prev_y,
                               const float* __restrict__ plan,
                               const float* __restrict__ ctx_e,
                               const float* __restrict__ ctx_s,
                               __half* __restrict__ ych)
{
    const int idx = blockIdx.x * blockDim.x + threadIdx.x;
    if (idx >= BSZ * YC) return;
    const int b = idx >> 10;
    const int c = idx & 1023;
    float v;
    if (c < EE) {
        v = prev_y[(size_t)b * EE + c];
    } else {
        const float p0 = plan[2 * b], p1 = plan[2 * b + 1];
        const int h = c - EE;
        v = p0 * ctx_e[(size_t)b * HH + h] + p1 * ctx_s[(size_t)b * HH + h];
    }
    ych[idx] = __float2half_rn(v);
}

// =================================================================================
// GRU cell elementwise; outputs out_hid (fp32) + hn fp16
// =================================================================================
__global__ void gru_kernel(const float* __restrict__ gx,
                           const float* __restrict__ ghbase,
                           const float* __restrict__ b_hh,
                           const float* __restrict__ prev_h,
                           float* __restrict__ out_hid,
                           __half* __restrict__ hnh)
{
    const int idx = blockIdx.x * blockDim.x + threadIdx.x;
    if (idx >= BSZ * DD) return;
    const int b = idx / DD;
    const int d = idx - b * DD;
    const float* gxb = gx + (size_t)b * G3D;
    const float* ghb = ghbase + (size_t)b * NCAT;
    const float ghr = ghb[d]          + b_hh[d];
    const float ghz = ghb[DD + d]     + b_hh[DD + d];
    const float ghn = ghb[2 * DD + d] + b_hh[2 * DD + d];
    const float r = 1.f / (1.f + expf(-(gxb[d] + ghr)));
    const float z = 1.f / (1.f + expf(-(gxb[DD + d] + ghz)));
    const float n = tanhf(gxb[2 * DD + d] + r * ghn);
    const float h = (1.f - z) * n + z * prev_h[idx];
    out_hid[idx] = h;
    hnh[idx] = __float2half_rn(h);
}

// =================================================================================
// host launcher — graph-capturable
// =================================================================================
extern "C" void kernel_launch(void* const* d_in, const int* in_sizes, int n_in,
                              void* d_out, int out_size)
{
    const float* prev_y  = (const float*)d_in[0];
    const float* prev_h  = (const float*)d_in[1];
    const float* equ_enc = (const float*)d_in[2];
    const float* sns_enc = (const float*)d_in[3];
    const int* equ_mask = (const int*)d_in[5];
    const int* sns_mask = (const int*)d_in[6];
    const float* W1e    = (const float*)d_in[7];
    const float* W2e    = (const float*)d_in[8];
    const float* vte    = (const float*)d_in[9];
    const float* W1s    = (const float*)d_in[10];
    const float* W2s    = (const float*)d_in[11];
    const float* vts    = (const float*)d_in[12];
    const float* plan_W = (const float*)d_in[13];
    const float* plan_b = (const float*)d_in[14];
    const float* Wc     = (const float*)d_in[15];
    const float* bc     = (const float*)d_in[16];
    const float* w_ih   = (const float*)d_in[17];
    const float* w_hh   = (const float*)d_in[18];
    const float* b_ih   = (const float*)d_in[19];
    const float* b_hh   = (const float*)d_in[20];
    const float* Wout   = (const float*)d_in[21];
    const float* bout   = (const float*)d_in[22];

    float* out      = (float*)d_out;
    float* out_dec  = out;
    float* out_hid  = out + (size_t)BSZ * VV;
    float* out_plan = out + (size_t)BSZ * VV + (size_t)BSZ * DD;

    float *u_e, *u_s, *ctx_e, *ctx_s, *plan, *gx, *dtgh;
    int *offE, *offS, *rowE, *rowS, *mtot;
    __half *ph_h, *ee_h, *es_h, *w1e_h, *w1s_h;
    __half *wcat_h, *wc_h, *wih_h, *yc_h, *x_h, *hn_h;
    cudaGetSymbolAddress((void**)&u_e,   g_u_e);
    cudaGetSymbolAddress((void**)&u_s,   g_u_s);
    cudaGetSymbolAddress((void**)&ctx_e, g_ctx_e);
    cudaGetSymbolAddress((void**)&ctx_s, g_ctx_s);
    cudaGetSymbolAddress((void**)&plan,  g_plan);
    cudaGetSymbolAddress((void**)&gx,    g_gx);
    cudaGetSymbolAddress((void**)&dtgh,  g_dtgh);
    cudaGetSymbolAddress((void**)&offE,  g_offE);
    cudaGetSymbolAddress((void**)&offS,  g_offS);
    cudaGetSymbolAddress((void**)&rowE,  g_rowE);
    cudaGetSymbolAddress((void**)&rowS,  g_rowS);
    cudaGetSymbolAddress((void**)&mtot,  g_mtot);
    cudaGetSymbolAddress((void**)&ph_h,  g_ph_h);
    cudaGetSymbolAddress((void**)&ee_h,  g_ee_h);   cudaGetSymbolAddress((void**)&es_h,  g_es_h);
    cudaGetSymbolAddress((void**)&w1e_h, g_w1e_h);  cudaGetSymbolAddress((void**)&w1s_h, g_w1s_h);
    cudaGetSymbolAddress((void**)&wcat_h, g_wcat_h);
    cudaGetSymbolAddress((void**)&wc_h,  g_wc_h);   cudaGetSymbolAddress((void**)&wih_h, g_wih_h);
    cudaGetSymbolAddress((void**)&yc_h,  g_yc_h);   cudaGetSymbolAddress((void**)&x_h,   g_x_h);
    cudaGetSymbolAddress((void**)&hn_h,  g_hn_h);

    cudaFuncSetAttribute(gemm_h64,  cudaFuncAttributeMaxDynamicSharedMemorySize, SMEM64H);
    cudaFuncSetAttribute(gemm_fp16, cudaFuncAttributeMaxDynamicSharedMemorySize, SMEM_H);
    cudaFuncSetAttribute(attn2h,    cudaFuncAttributeMaxDynamicSharedMemorySize, SMEM_H);

    const dim3 blk(256);

    compact_kernel<<<1, 256>>>(equ_mask, sns_mask, offE, offS, mtot);
    gather2<<<dim3(BSZ, 2), 256>>>(equ_enc, sns_enc, equ_mask, sns_mask, offE, offS,
                                   ee_h, es_h, rowE, rowS, u_e, u_s);

    {
        CvtArgs ca;
        ca.seg[0] = { prev_h, ph_h, BSZ * DD / 4 };
        ca.seg[1] = { W2e,  wcat_h,                       HH * DD / 4 };
        ca.seg[2] = { W2s,  wcat_h + (size_t)HH * DD,     HH * DD / 4 };
        ca.seg[3] = { w_hh, wcat_h + (size_t)2 * HH * DD, G3D * DD / 4 };
        ca.seg[4] = { Wc,   wc_h,  HH * YC / 4 };
        ca.seg[5] = { w_ih, wih_h, G3D * HH / 4 };
        ca.seg[6] = { W1e,  w1e_h, HH * HH / 4 };
        ca.seg[7] = { W1s,  w1s_h, HH * HH / 4 };
        const int maxb = (G3D * DD / 4 + 255) / 256;
        cvt_all<<<dim3(maxb, 8), blk>>>(ca);
    }

    gemm_h64<<<dim3(NCAT / 128, BSZ / 64), blk, SMEM64H>>>(
        ph_h, wcat_h, nullptr, dtgh, nullptr, BSZ, NCAT, DD);

    plan_kernel<<<BSZ, 256>>>(prev_h, plan_W, plan_b, plan, out_plan);

    attn2h<<<dim3(BSZ, 2), blk, SMEM_H>>>(
        ee_h, es_h, w1e_h, w1s_h, dtgh, vte, vts, rowE, rowS, mtot, u_e, u_s);

    softmax_ctx2<<<dim3(BSZ, 2), blk>>>(u_e, u_s, equ_enc, sns_enc, ctx_e, ctx_s);

    combine_kernel<<<(BSZ * YC) / 256, blk>>>(prev_y, plan, ctx_e, ctx_s, yc_h);

    gemm_h64<<<dim3(HH / 128, BSZ / 64), blk, SMEM64H>>>(
        yc_h, wc_h, bc, nullptr, x_h, BSZ, HH, YC);
    gemm_h64<<<dim3(G3D / 128, BSZ / 64), blk, SMEM64H>>>(
        x_h, wih_h, b_ih, gx, nullptr, BSZ, G3D, HH);

    gru_kernel<<<(BSZ * DD) / 256, blk>>>(gx, dtgh + 2 * HH, b_hh, prev_h, out_hid, hn_h);

    gemm_fp16<<<dim3(VV / 128, BSZ / 128), blk, SMEM_H>>>(
        hn_h, Wout, bout, out_dec, BSZ, VV, DD);
}

// round 16
// speedup vs baseline: 6.0814x; 1.0548x over previous
#include <cuda_runtime.h>
#include <cuda_fp16.h>
#include <math.h>
#include <stdint.h>

#define HH   512
#define ZZ   128
#define EE   512
#define DD   1152      // 2H + Z
#define VV   32000
#define BSZ  256
#define NN   128
#define G3D  3456      // 3*D
#define NCAT 4480      // 512 (dt_e) + 512 (dt_s) + 3456 (gh)
#define YC   1024      // E + H

// ---------------- scratch (device globals; no allocation allowed) ----------------
__device__ float g_u_e  [BSZ * NN];
__device__ float g_u_s  [BSZ * NN];
__device__ float g_ctx_e[BSZ * HH];
__device__ float g_ctx_s[BSZ * HH];
__device__ float g_plan [BSZ * 2];
__device__ float g_gx   [BSZ * G3D];
__device__ float g_dtgh [BSZ * NCAT];
__device__ int   g_offE [BSZ];
__device__ int   g_offS [BSZ];
__device__ int   g_rowE [BSZ * NN];
__device__ int   g_rowS [BSZ * NN];
__device__ int   g_mtot [2];

// fp16 operands (16B-aligned for cp.async / ldmatrix)
__device__ __align__(256) __half g_ph_h  [BSZ * DD];
__device__ __align__(256) __half g_ee_h  [BSZ * NN * HH];
__device__ __align__(256) __half g_es_h  [BSZ * NN * HH];
__device__ __align__(256) __half g_w1e_h [HH * HH];
__device__ __align__(256) __half g_w1s_h [HH * HH];
__device__ __align__(256) __half g_wcat_h[NCAT * DD];
__device__ __align__(256) __half g_wc_h  [HH * YC];
__device__ __align__(256) __half g_wih_h [G3D * HH];
__device__ __align__(256) __half g_yc_h  [BSZ * YC];
__device__ __align__(256) __half g_x_h   [BSZ * HH];
__device__ __align__(256) __half g_hn_h  [BSZ * DD];

// ---------------- helpers ----------------
__device__ __forceinline__ uint32_t pack_h2(float a, float b) {
    __half2 t = __floats2half2_rn(a, b);
    return *reinterpret_cast<uint32_t*>(&t);
}

__device__ __forceinline__ void mma16816h(float c[4],
                                          uint32_t a0, uint32_t a1, uint32_t a2, uint32_t a3,
                                          uint32_t b0, uint32_t b1) {
    asm volatile(
        "mma.sync.aligned.m16n8k16.row.col.f32.f16.f16.f32 "
        "{%0,%1,%2,%3}, {%4,%5,%6,%7}, {%8,%9}, {%0,%1,%2,%3};\n"
        : "+f"(c[0]), "+f"(c[1]), "+f"(c[2]), "+f"(c[3])
        : "r"(a0), "r"(a1), "r"(a2), "r"(a3), "r"(b0), "r"(b1));
}

__device__ __forceinline__ void ldsm_x4(uint32_t& r0, uint32_t& r1, uint32_t& r2, uint32_t& r3,
                                        uint32_t addr) {
    asm volatile("ldmatrix.sync.aligned.m8n8.x4.shared.b16 {%0,%1,%2,%3}, [%4];"
                 : "=r"(r0), "=r"(r1), "=r"(r2), "=r"(r3) : "r"(addr));
}
__device__ __forceinline__ void ldsm_x2(uint32_t& r0, uint32_t& r1, uint32_t addr) {
    asm volatile("ldmatrix.sync.aligned.m8n8.x2.shared.b16 {%0,%1}, [%2];"
                 : "=r"(r0), "=r"(r1) : "r"(addr));
}

#define CP16(dst, src) \
    asm volatile("cp.async.cg.shared.global [%0], [%1], 16;" :: "r"(dst), "l"(src))
#define CP_COMMIT() asm volatile("cp.async.commit_group;")
#define CP_WAIT2()  asm volatile("cp.async.wait_group 2;")

#define SMS 40
#define STG (128 * SMS)
#define STGB_H (STG * 2)            // 128-row fp16 array = 10240 bytes
#define STAGE_H (2 * STGB_H)        // A(128) + B(128) per stage = 20480
#define SMEM_H (4 * STAGE_H)        // 4-stage: 81920

// BM=64 fp16 constants
#define A64HB (64 * SMS * 2)        // 5120 bytes
#define S64HB (A64HB + STGB_H)      // 15360 per stage
#define SMEM64H (4 * S64HB)         // 4-stage: 61440

__device__ __forceinline__ uint32_t ldsm_aoff(int l) {
    return (uint32_t)((((l & 7) + ((l >> 3) & 1) * 8) * SMS + (l >> 4) * 8) * 2);
}
__device__ __forceinline__ uint32_t ldsm_boff(int l) {
    return (uint32_t)(((l & 7) * SMS + ((l >> 3) & 1) * 8) * 2);
}

// =================================================================================
// gemm_h64: BM=64 x BN=128 fp16 GEMM, both operands pre-converted.
// 4-stage cp.async pipeline; one barrier per chunk; fill post-barrier.
// =================================================================================
__global__ void __launch_bounds__(256, 2) gemm_h64(
    const __half* __restrict__ A, const __half* __restrict__ B,
    const float* __restrict__ bias,
    float* __restrict__ C, __half* __restrict__ Ch,
    int M, int N, int K)
{
    extern __shared__ __half smh[];

    const int t    = threadIdx.x;
    const int m0   = blockIdx.y * 64;
    const int n0   = blockIdx.x * 128;
    const int lane = t & 31;
    const int wid  = t >> 5;
    const int g    = lane >> 2;
    const int tg   = lane & 3;
    const int wr   = wid & 1;
    const int wc   = wid >> 1;

    const uint32_t smb  = (uint32_t)__cvta_generic_to_shared(smh);
    const uint32_t aoff = ldsm_aoff(lane);
    const uint32_t boff = ldsm_boff(lane);

    const int ar = t >> 2;
    const int ac = (t & 3) * 8;
    const uint32_t atoff = (uint32_t)(ar * SMS + ac) * 2;
    const int br = t >> 1;
    const int bc = (t & 1) * 16;
    const uint32_t btoff = (uint32_t)(br * SMS + bc) * 2;

    const __half* Ap = A + (size_t)(m0 + ar) * K + ac;
    const __half* Bp = B + (size_t)(n0 + br) * K + bc;

    float acc[2][4][4];
#pragma unroll
    for (int mi = 0; mi < 2; mi++)
#pragma unroll
        for (int ni = 0; ni < 4; ni++)
#pragma unroll
            for (int q = 0; q < 4; q++) acc[mi][ni][q] = 0.f;

#define FILLH64(D, K0)                                   \
    do {                                                 \
        CP16((D) + atoff,              Ap + (K0));       \
        CP16((D) + A64HB + btoff,      Bp + (K0));       \
        CP16((D) + A64HB + btoff + 16, Bp + (K0) + 8);   \
    } while (0)

    const int NC = K >> 5;
#pragma unroll
    for (int i = 0; i < 3; i++) {
        if (i < NC) FILLH64(smb + (uint32_t)i * S64HB, i * 32);
        CP_COMMIT();
    }

    for (int c = 0; c < NC; c++) {
        CP_WAIT2();
        __syncthreads();
        if (c + 3 < NC) FILLH64(smb + (uint32_t)((c + 3) & 3) * S64HB, (c + 3) * 32);
        CP_COMMIT();
        const uint32_t stb = smb + (uint32_t)(c & 3) * S64HB;
#pragma unroll
        for (int ks = 0; ks < 2; ks++) {
            const uint32_t kb2 = ks * 32;
            uint32_t bf[4][2];
#pragma unroll
            for (int ni = 0; ni < 4; ni++) {
                const uint32_t rb = (uint32_t)(wc * 32 + ni * 8) * (SMS * 2) + kb2 + boff;
                ldsm_x2(bf[ni][0], bf[ni][1], stb + A64HB + rb);
            }
#pragma unroll
            for (int mi = 0; mi < 2; mi++) {
                const uint32_t ra = (uint32_t)(wr * 32 + mi * 16) * (SMS * 2) + kb2 + aoff;
                uint32_t a0, a1, a2, a3;
                ldsm_x4(a0, a1, a2, a3, stb + ra);
#pragma unroll
                for (int ni = 0; ni < 4; ni++)
                    mma16816h(acc[mi][ni], a0, a1, a2, a3, bf[ni][0], bf[ni][1]);
            }
        }
    }

#pragma unroll
    for (int mi = 0; mi < 2; mi++) {
        const int row = m0 + wr * 32 + mi * 16 + g;
#pragma unroll
        for (int ni = 0; ni < 4; ni++) {
            const int col = n0 + wc * 32 + ni * 8 + tg * 2;
            float b0 = bias ? bias[col] : 0.f;
            float b1 = bias ? bias[col + 1] : 0.f;
            float c00 = acc[mi][ni][0] + b0, c01 = acc[mi][ni][1] + b1;
            float c10 = acc[mi][ni][2] + b0, c11 = acc[mi][ni][3] + b1;
            if (C) {
                *(float2*)&C[(size_t)row * N + col]       = make_float2(c00, c01);
                *(float2*)&C[(size_t)(row + 8) * N + col] = make_float2(c10, c11);
            }
            if (Ch) {
                *(uint32_t*)&Ch[(size_t)row * N + col]       = pack_h2(c00, c01);
                *(uint32_t*)&Ch[(size_t)(row + 8) * N + col] = pack_h2(c10, c11);
            }
        }
    }
}

// =================================================================================
// gemm_fp16: Wout GEMM (BM=128).  M-FASTEST GRID: blockIdx.x = m-tile (2),
// blockIdx.y = n-tile (250) — the two CTAs sharing a B n-tile are adjacent in
// issue order, so the second read of each fp32 B tile hits L2 (halves B DRAM).
// A fp16 4-stage cp.async; B fp32 LDG -> fp16 smem one chunk ahead.
// =================================================================================
__global__ void __launch_bounds__(256, 2) gemm_fp16(
    const __half* __restrict__ A, const float* __restrict__ B,
    const float* __restrict__ bias, float* __restrict__ C,
    int M, int N, int K)
{
    extern __shared__ __half smh[];

    const int t    = threadIdx.x;
    const int m0   = blockIdx.x * 128;   // m fastest
    const int n0   = blockIdx.y * 128;
    const int lane = t & 31;
    const int wid  = t >> 5;
    const int g    = lane >> 2;
    const int tg   = lane & 3;
    const int wr   = wid & 1;
    const int wc   = wid >> 1;

    const uint32_t smb  = (uint32_t)__cvta_generic_to_shared(smh);
    const uint32_t aoff = ldsm_aoff(lane);
    const uint32_t boff = ldsm_boff(lane);

    const int r  = t >> 1;
    const int hh = (t & 1) * 16;
    const uint32_t toff = (uint32_t)(r * SMS + hh) * 2;
    const int idx = r * SMS + hh;
    const __half* Ap = A + (size_t)(m0 + r) * K + hh;
    const float*  Bp = B + (size_t)(n0 + r) * K + hh;

    float acc[4][4][4];
#pragma unroll
    for (int mi = 0; mi < 4; mi++)
#pragma unroll
        for (int ni = 0; ni < 4; ni++)
#pragma unroll
            for (int q = 0; q < 4; q++) acc[mi][ni][q] = 0.f;

#define CVTB_H(ST, RB)                                                        \
    do {                                                                      \
        __half* bdst = smh + (ST) * (STAGE_H / 2) + (STGB_H / 2) + idx;       \
        uint4 v0, v1;                                                         \
        v0.x = pack_h2((RB)[0].x, (RB)[0].y); v0.y = pack_h2((RB)[0].z, (RB)[0].w); \
        v0.z = pack_h2((RB)[1].x, (RB)[1].y); v0.w = pack_h2((RB)[1].z, (RB)[1].w); \
        v1.x = pack_h2((RB)[2].x, (RB)[2].y); v1.y = pack_h2((RB)[2].z, (RB)[2].w); \
        v1.z = pack_h2((RB)[3].x, (RB)[3].y); v1.w = pack_h2((RB)[3].z, (RB)[3].w); \
        *(uint4*)bdst       = v0;                                             \
        *(uint4*)(bdst + 8) = v1;                                             \
    } while (0)

    const int NC = K >> 5;

    // B chunk 0 -> stage 0 (visible after iter-0 barrier)
    {
        float4 rb0[4];
#pragma unroll
        for (int i = 0; i < 4; i++) rb0[i] = *(const float4*)(Bp + i * 4);
        CVTB_H(0, rb0);
    }
    // A prologue: stages 0..2
#pragma unroll
    for (int i = 0; i < 3; i++) {
        if (i < NC) {
            const uint32_t d = smb + (uint32_t)i * STAGE_H + toff;
            CP16(d,      Ap + i * 32);
            CP16(d + 16, Ap + i * 32 + 8);
        }
        CP_COMMIT();
    }

    for (int c = 0; c < NC; c++) {
        CP_WAIT2();
        __syncthreads();
        if (c + 3 < NC) {
            const uint32_t d = smb + (uint32_t)((c + 3) & 3) * STAGE_H + toff;
            CP16(d,      Ap + (c + 3) * 32);
            CP16(d + 16, Ap + (c + 3) * 32 + 8);
        }
        CP_COMMIT();
        float4 rb[4];
        const bool moreB = (c + 1 < NC);
        if (moreB) {
#pragma unroll
            for (int i = 0; i < 4; i++) rb[i] = *(const float4*)(Bp + (c + 1) * 32 + i * 4);
        }
        const uint32_t stb = smb + (uint32_t)(c & 3) * STAGE_H;
#pragma unroll
        for (int ks = 0; ks < 2; ks++) {
            const uint32_t kb2 = ks * 32;
            uint32_t bf[4][2];
#pragma unroll
            for (int ni = 0; ni < 4; ni++) {
                const uint32_t rbo = (uint32_t)(wc * 32 + ni * 8) * (SMS * 2) + kb2 + boff;
                ldsm_x2(bf[ni][0], bf[ni][1], stb + STGB_H + rbo);
            }
#pragma unroll
            for (int mi = 0; mi < 4; mi++) {
                const uint32_t ra = (uint32_t)(wr * 64 + mi * 16) * (SMS * 2) + kb2 + aoff;
                uint32_t a0, a1, a2, a3;
                ldsm_x4(a0, a1, a2, a3, stb + ra);
#pragma unroll
                for (int ni = 0; ni < 4; ni++)
                    mma16816h(acc[mi][ni], a0, a1, a2, a3, bf[ni][0], bf[ni][1]);
            }
        }
        if (moreB) CVTB_H((c + 1) & 3, rb);
    }

#pragma unroll
    for (int mi = 0; mi < 4; mi++) {
        const int row = m0 + wr * 64 + mi * 16 + g;
#pragma unroll
        for (int ni = 0; ni < 4; ni++) {
            const int col = n0 + wc * 32 + ni * 8 + tg * 2;
            const float b0 = bias[col], b1 = bias[col + 1];
            *(float2*)&C[(size_t)row * N + col] =
                make_float2(acc[mi][ni][0] + b0, acc[mi][ni][1] + b1);
            *(float2*)&C[(size_t)(row + 8) * N + col] =
                make_float2(acc[mi][ni][2] + b0, acc[mi][ni][3] + b1);
        }
    }
}

// =================================================================================
// cvt_all: batched fp32 -> fp16 conversion (grid.y = segment)
// =================================================================================
struct CvtSeg { const float* src; __half* dst; int n4; };
struct CvtArgs { CvtSeg seg[8]; };

__global__ void cvt_all(CvtArgs a)
{
    const CvtSeg s = a.seg[blockIdx.y];
    const int i = blockIdx.x * blockDim.x + threadIdx.x;
    if (i >= s.n4) return;
    float4 v = ((const float4*)s.src)[i];
    uint2 o;
    o.x = pack_h2(v.x, v.y);
    o.y = pack_h2(v.z, v.w);
    ((uint2*)s.dst)[i] = o;
}

// =================================================================================
// compact: per-batch exclusive offsets of unmasked positions (both masks)
// =================================================================================
__global__ void compact_kernel(const int* __restrict__ mE, const int* __restrict__ mS,
                               int* __restrict__ offE, int* __restrict__ offS,
                               int* __restrict__ mtot)
{
    __shared__ int sE[256], sS[256];
    const int b = threadIdx.x;
    int cE = 0, cS = 0;
    for (int n = 0; n < NN; n++) {
        cE += (mE[b * NN + n] == 0);
        cS += (mS[b * NN + n] == 0);
    }
    sE[b] = cE; sS[b] = cS;
    __syncthreads();
    for (int d = 1; d < 256; d <<= 1) {
        int vE = 0, vS = 0;
        if (b >= d) { vE = sE[b - d]; vS = sS[b - d]; }
        __syncthreads();
        sE[b] += vE; sS[b] += vS;
        __syncthreads();
    }
    offE[b] = sE[b] - cE;
    offS[b] = sS[b] - cS;
    if (b == 255) { mtot[0] = sE[255]; mtot[1] = sS[255]; }
}

// =================================================================================
// merged gather (grid.y = side): compact unmasked enc rows -> fp16
// =================================================================================
__global__ void gather2(const float* __restrict__ encE, const float* __restrict__ encS,
                        const int* __restrict__ mE, const int* __restrict__ mS,
                        const int* __restrict__ offE, const int* __restrict__ offS,
                        __half* __restrict__ geh, __half* __restrict__ gsh,
                        int* __restrict__ rowE, int* __restrict__ rowS,
                        float* __restrict__ uE, float* __restrict__ uS)
{
    const int side = blockIdx.y;
    const float* enc = side ? encS : encE;
    const int* mask  = side ? mS : mE;
    const int* off   = side ? offS : offE;
    __half* gh = side ? gsh : geh;
    int* rowinfo = side ? rowS : rowE;
    float* u     = side ? uS : uE;

    __shared__ int s_list[NN];
    __shared__ int s_wtot[8];
    const int b = blockIdx.x;
    const int t = threadIdx.x;
    const int base = off[b];
    const bool in = t < NN;
    const bool valid = in && (mask[b * NN + t] == 0);
    const unsigned wm = __ballot_sync(0xffffffffu, valid);
    const int lane = t & 31, w = t >> 5;
    if (lane == 0) s_wtot[w] = __popc(wm);
    __syncthreads();
    int wbase = 0;
#pragma unroll
    for (int i = 0; i < 4; i++) if (i < w) wbase += s_wtot[i];
    const int rank = wbase + __popc(wm & ((1u << lane) - 1));
    if (valid) {
        s_list[rank] = t;
        rowinfo[base + rank] = b * NN + t;
    } else if (in) {
        u[b * NN + t] = -INFINITY;
    }
    __syncthreads();
    const int cnt = s_wtot[0] + s_wtot[1] + s_wtot[2] + s_wtot[3];

    for (int i = 0; i < cnt; i++) {
        const int n = s_list[i];
        const float2 v = *(const float2*)(enc + ((size_t)b * NN + n) * HH + t * 2);
        *(uint32_t*)&gh[((size_t)base + i) * HH + t * 2] = pack_h2(v.x, v.y);
    }
}

// =================================================================================
// merged attention, fp16 single-pass, 4-stage pipeline (grid = (256, 2)).
// =================================================================================
__global__ void __launch_bounds__(256, 2) attn2h(
    const __half* __restrict__ geh, const __half* __restrict__ gsh,
    const __half* __restrict__ w1eh, const __half* __restrict__ w1sh,
    const float* __restrict__ dtg,
    const float* __restrict__ vte, const float* __restrict__ vts,
    const int* __restrict__ rowE, const int* __restrict__ rowS,
    const int* __restrict__ mtotp,
    float* __restrict__ uE, float* __restrict__ uS)
{
    extern __shared__ __half smh[];
    __shared__ float s_vt[512];
    __shared__ float s_u[128];

    const int side = blockIdx.y;
    const int mtot = mtotp[side];
    const int m0 = blockIdx.x * 128;
    if (m0 >= mtot) return;

    const __half* ge  = side ? gsh : geh;
    const __half* w1h = side ? w1sh : w1eh;
    const float* vt = side ? vts : vte;
    const int* rowinfo = side ? rowS : rowE;
    float* u = side ? uS : uE;

    const int t    = threadIdx.x;
    const int lane = t & 31;
    const int wid  = t >> 5;
    const int g    = lane >> 2;
    const int tg   = lane & 3;
    const int wr   = wid & 1;
    const int wc   = wid >> 1;

    const uint32_t smb  = (uint32_t)__cvta_generic_to_shared(smh);
    const uint32_t aoff = ldsm_aoff(lane);
    const uint32_t boff = ldsm_boff(lane);

    for (int i = t; i < 512; i += 256) s_vt[i] = vt[i];
    if (t < 128) s_u[t] = 0.f;

    int rb4[4][2];
#pragma unroll
    for (int mi = 0; mi < 4; mi++)
#pragma unroll
        for (int rr = 0; rr < 2; rr++)
            rb4[mi][rr] = rowinfo[m0 + wr * 64 + mi * 16 + g + rr * 8] >> 7;

    const int r  = t >> 1;
    const int hh = (t & 1) * 16;
    const uint32_t toff = (uint32_t)(r * SMS + hh) * 2;
    const __half* Ap = ge + (size_t)(m0 + r) * 512 + hh;

    float up[8];
#pragma unroll
    for (int i = 0; i < 8; i++) up[i] = 0.f;

#define AFILL(ST, K0)                                          \
    do {                                                       \
        const uint32_t d = smb + (uint32_t)(ST) * STAGE_H;     \
        CP16(d + toff,               Ap + (K0));               \
        CP16(d + toff + 16,          Ap + (K0) + 8);           \
        CP16(d + STGB_H + toff,      Bp + (K0));               \
        CP16(d + STGB_H + toff + 16, Bp + (K0) + 8);           \
    } while (0)

    for (int nc = 0; nc < 4; nc++) {
        const __half* Bp = w1h + (size_t)(nc * 128 + r) * 512 + hh;

        float acc[4][4][4];
#pragma unroll
        for (int mi = 0; mi < 4; mi++)
#pragma unroll
            for (int ni = 0; ni < 4; ni++)
#pragma unroll
                for (int q = 0; q < 4; q++) acc[mi][ni][q] = 0.f;

        __syncthreads();   // all warps past previous nc's mma before refilling
#pragma unroll
        for (int i = 0; i < 3; i++) {
            AFILL(i, i * 32);
            CP_COMMIT();
        }

        for (int c = 0; c < 16; c++) {
            CP_WAIT2();
            __syncthreads();
            if (c + 3 < 16) AFILL((c + 3) & 3, (c + 3) * 32);
            CP_COMMIT();
            const uint32_t stb = smb + (uint32_t)(c & 3) * STAGE_H;
#pragma unroll
            for (int ks = 0; ks < 2; ks++) {
                const uint32_t kb2 = ks * 32;
                uint32_t bf[4][2];
#pragma unroll
                for (int ni = 0; ni < 4; ni++) {
                    const uint32_t rbo = (uint32_t)(wc * 32 + ni * 8) * (SMS * 2) + kb2 + boff;
                    ldsm_x2(bf[ni][0], bf[ni][1], stb + STGB_H + rbo);
                }
#pragma unroll
                for (int mi = 0; mi < 4; mi++) {
                    const uint32_t ra = (uint32_t)(wr * 64 + mi * 16) * (SMS * 2) + kb2 + aoff;
                    uint32_t a0, a1, a2, a3;
                    ldsm_x4(a0, a1, a2, a3, stb + ra);
#pragma unroll
                    for (int ni = 0; ni < 4; ni++)
                        mma16816h(acc[mi][ni], a0, a1, a2, a3, bf[ni][0], bf[ni][1]);
                }
            }
        }

#pragma unroll
        for (int mi = 0; mi < 4; mi++) {
            const float* dt0 = dtg + (size_t)rb4[mi][0] * NCAT + (side ? HH : 0);
            const float* dt1 = dtg + (size_t)rb4[mi][1] * NCAT + (side ? HH : 0);
#pragma unroll
            for (int ni = 0; ni < 4; ni++) {
                const int col = nc * 128 + wc * 32 + ni * 8 + tg * 2;
                const float v0 = s_vt[col], v1 = s_vt[col + 1];
                up[mi * 2 + 0] += v0 * tanhf(acc[mi][ni][0] + dt0[col])
                                + v1 * tanhf(acc[mi][ni][1] + dt0[col + 1]);
                up[mi * 2 + 1] += v0 * tanhf(acc[mi][ni][2] + dt1[col])
                                + v1 * tanhf(acc[mi][ni][3] + dt1[col + 1]);
            }
        }
    }

#pragma unroll
    for (int mi = 0; mi < 4; mi++)
#pragma unroll
        for (int rr = 0; rr < 2; rr++) {
            float v = up[mi * 2 + rr];
            v += __shfl_down_sync(0xffffffffu, v, 1);
            v += __shfl_down_sync(0xffffffffu, v, 2);
            if (tg == 0)
                atomicAdd(&s_u[wr * 64 + mi * 16 + g + rr * 8], v);
        }
    __syncthreads();

    if (t < 128 && m0 + t < mtot)
        u[rowinfo[m0 + t]] = s_u[t];
}

// =================================================================================
// plan = softmax(prev_h @ plan_W^T + plan_b)   (256 threads, float4)
// =================================================================================
__global__ void plan_kernel(const float* __restrict__ prev_h,
                            const float* __restrict__ plan_W,
                            const float* __restrict__ plan_b,
                            float* __restrict__ plan,
                            float* __restrict__ out_plan)
{
    const int b = blockIdx.x;
    const int t = threadIdx.x;
    __shared__ float s0[256], s1[256];
    float a0 = 0.f, a1 = 0.f;
    const float4* hb = (const float4*)(prev_h + (size_t)b * DD);
    const float4* w0 = (const float4*)plan_W;
    const float4* w1 = (const float4*)(plan_W + DD);
    for (int k = t; k < DD / 4; k += 256) {
        const float4 h = hb[k], x = w0[k], y = w1[k];
        a0 += h.x * x.x + h.y * x.y + h.z * x.z + h.w * x.w;
        a1 += h.x * y.x + h.y * y.y + h.z * y.z + h.w * y.w;
    }
    s0[t] = a0; s1[t] = a1;
    __syncthreads();
    for (int s = 128; s > 0; s >>= 1) {
        if (t < s) { s0[t] += s0[t + s]; s1[t] += s1[t + s]; }
        __syncthreads();
    }
    if (t == 0) {
        const float l0 = s0[0] + plan_b[0];
        const float l1 = s1[0] + plan_b[1];
        const float mx = fmaxf(l0, l1);
        const float e0 = expf(l0 - mx), e1 = expf(l1 - mx);
        const float inv = 1.f / (e0 + e1);
        plan[2 * b] = e0 * inv;       plan[2 * b + 1] = e1 * inv;
        out_plan[2 * b] = e0 * inv;   out_plan[2 * b + 1] = e1 * inv;
    }
}

// =================================================================================
// merged softmax+context (grid = (BSZ, 2)) — reads the gathered fp16 rows
// (contiguous, half traffic).  s_aw rank order == gather rank order (same
// ballot over mask==0), so aw[i] pairs with gathered row base+i.
// =================================================================================
__global__ void softmax_ctx2(const float* __restrict__ uE, const float* __restrict__ uS,
                             const __half* __restrict__ geh, const __half* __restrict__ gsh,
                             const int* __restrict__ offE, const int* __restrict__ offS,
                             float* __restrict__ ctxE, float* __restrict__ ctxS)
{
    const int side = blockIdx.y;
    const float* u  = side ? uS : uE;
    const __half* gh = side ? gsh : geh;
    const int* off  = side ? offS : offE;
    float* ctx      = side ? ctxS : ctxE;

    const int b = blockIdx.x;
    const int t = threadIdx.x;
    __shared__ float red[256];
    __shared__ float s_aw[NN];
    __shared__ int   s_wtot[4];

    const float uv = (t < NN) ? u[(size_t)b * NN + t] : -INFINITY;
    red[t] = uv;
    __syncthreads();
    for (int s = 128; s > 0; s >>= 1) {
        if (t < s) red[t] = fmaxf(red[t], red[t + s]);
        __syncthreads();
    }
    const float mx = red[0];
    __syncthreads();
    const float e = (t < NN) ? expf(uv - mx) : 0.f;
    red[t] = e;
    __syncthreads();
    for (int s = 128; s > 0; s >>= 1) {
        if (t < s) red[t] += red[t + s];
        __syncthreads();
    }
    const float inv = 1.f / red[0];

    const bool valid = (t < NN) && (uv != -INFINITY);
    const unsigned wm = __ballot_sync(0xffffffffu, valid);
    const int lane = t & 31, w = t >> 5;
    if (lane == 0 && w < 4) s_wtot[w] = __popc(wm);
    __syncthreads();
    int wbase = 0;
#pragma unroll
    for (int i = 0; i < 4; i++) if (i < w) wbase += s_wtot[i];
    if (valid) {
        const int rank = wbase + __popc(wm & ((1u << lane) - 1));
        s_aw[rank] = e * inv;
    }
    __syncthreads();
    const int cnt = s_wtot[0] + s_wtot[1] + s_wtot[2] + s_wtot[3];
    const int base = off[b];

    const __half* gb = gh + (size_t)base * HH;
    for (int h = t; h < HH; h += 256) {
        float s = 0.f;
        for (int i = 0; i < cnt; i++)
            s += s_aw[i] * __half2float(gb[(size_t)i * HH + h]);
        ctx[(size_t)b * HH + h] = s;
    }
}

// =================================================================================
// y_ctx = [prev_y | plan0*ctx_e + plan1*ctx_s], written fp16
// =================================================================================
__global__ void combine_kernel(const float* __restrict__ prev_y,
                               const float* __restrict__ plan,
                               const float* __restrict__ ctx_e,
                               const float* __restrict__ ctx_s,
                               __half* __restrict__ ych)
{
    const int idx = blockIdx.x * blockDim.x + threadIdx.x;
    if (idx >= BSZ * YC) return;
    const int b = idx >> 10;
    const int c = idx & 1023;
    float v;
    if (c < EE) {
        v = prev_y[(size_t)b * EE + c];
    } else {
        const float p0 = plan[2 * b], p1 = plan[2 * b + 1];
        const int h = c - EE;
        v = p0 * ctx_e[(size_t)b * HH + h] + p1 * ctx_s[(size_t)b * HH + h];
    }
    ych[idx] = __float2half_rn(v);
}

// =================================================================================
// GRU cell elementwise; outputs out_hid (fp32) + hn fp16
// =================================================================================
__global__ void gru_kernel(const float* __restrict__ gx,
                           const float* __restrict__ ghbase,
                           const float* __restrict__ b_hh,
                           const float* __restrict__ prev_h,
                           float* __restrict__ out_hid,
                           __half* __restrict__ hnh)
{
    const int idx = blockIdx.x * blockDim.x + threadIdx.x;
    if (idx >= BSZ * DD) return;
    const int b = idx / DD;
    const int d = idx - b * DD;
    const float* gxb = gx + (size_t)b * G3D;
    const float* ghb = ghbase + (size_t)b * NCAT;
    const float ghr = ghb[d]          + b_hh[d];
    const float ghz = ghb[DD + d]     + b_hh[DD + d];
    const float ghn = ghb[2 * DD + d] + b_hh[2 * DD + d];
    const float r = 1.f / (1.f + expf(-(gxb[d] + ghr)));
    const float z = 1.f / (1.f + expf(-(gxb[DD + d] + ghz)));
    const float n = tanhf(gxb[2 * DD + d] + r * ghn);
    const float h = (1.f - z) * n + z * prev_h[idx];
    out_hid[idx] = h;
    hnh[idx] = __float2half_rn(h);
}

// =================================================================================
// host launcher — graph-capturable
// =================================================================================
extern "C" void kernel_launch(void* const* d_in, const int* in_sizes, int n_in,
                              void* d_out, int out_size)
{
    const float* prev_y  = (const float*)d_in[0];
    const float* prev_h  = (const float*)d_in[1];
    const float* equ_enc = (const float*)d_in[2];
    const float* sns_enc = (const float*)d_in[3];
    const int* equ_mask = (const int*)d_in[5];
    const int* sns_mask = (const int*)d_in[6];
    const float* W1e    = (const float*)d_in[7];
    const float* W2e    = (const float*)d_in[8];
    const float* vte    = (const float*)d_in[9];
    const float* W1s    = (const float*)d_in[10];
    const float* W2s    = (const float*)d_in[11];
    const float* vts    = (const float*)d_in[12];
    const float* plan_W = (const float*)d_in[13];
    const float* plan_b = (const float*)d_in[14];
    const float* Wc     = (const float*)d_in[15];
    const float* bc     = (const float*)d_in[16];
    const float* w_ih   = (const float*)d_in[17];
    const float* w_hh   = (const float*)d_in[18];
    const float* b_ih   = (const float*)d_in[19];
    const float* b_hh   = (const float*)d_in[20];
    const float* Wout   = (const float*)d_in[21];
    const float* bout   = (const float*)d_in[22];

    float* out      = (float*)d_out;
    float* out_dec  = out;
    float* out_hid  = out + (size_t)BSZ * VV;
    float* out_plan = out + (size_t)BSZ * VV + (size_t)BSZ * DD;

    float *u_e, *u_s, *ctx_e, *ctx_s, *plan, *gx, *dtgh;
    int *offE, *offS, *rowE, *rowS, *mtot;
    __half *ph_h, *ee_h, *es_h, *w1e_h, *w1s_h;
    __half *wcat_h, *wc_h, *wih_h, *yc_h, *x_h, *hn_h;
    cudaGetSymbolAddress((void**)&u_e,   g_u_e);
    cudaGetSymbolAddress((void**)&u_s,   g_u_s);
    cudaGetSymbolAddress((void**)&ctx_e, g_ctx_e);
    cudaGetSymbolAddress((void**)&ctx_s, g_ctx_s);
    cudaGetSymbolAddress((void**)&plan,  g_plan);
    cudaGetSymbolAddress((void**)&gx,    g_gx);
    cudaGetSymbolAddress((void**)&dtgh,  g_dtgh);
    cudaGetSymbolAddress((void**)&offE,  g_offE);
    cudaGetSymbolAddress((void**)&offS,  g_offS);
    cudaGetSymbolAddress((void**)&rowE,  g_rowE);
    cudaGetSymbolAddress((void**)&rowS,  g_rowS);
    cudaGetSymbolAddress((void**)&mtot,  g_mtot);
    cudaGetSymbolAddress((void**)&ph_h,  g_ph_h);
    cudaGetSymbolAddress((void**)&ee_h,  g_ee_h);   cudaGetSymbolAddress((void**)&es_h,  g_es_h);
    cudaGetSymbolAddress((void**)&w1e_h, g_w1e_h);  cudaGetSymbolAddress((void**)&w1s_h, g_w1s_h);
    cudaGetSymbolAddress((void**)&wcat_h, g_wcat_h);
    cudaGetSymbolAddress((void**)&wc_h,  g_wc_h);   cudaGetSymbolAddress((void**)&wih_h, g_wih_h);
    cudaGetSymbolAddress((void**)&yc_h,  g_yc_h);   cudaGetSymbolAddress((void**)&x_h,   g_x_h);
    cudaGetSymbolAddress((void**)&hn_h,  g_hn_h);

    cudaFuncSetAttribute(gemm_h64,  cudaFuncAttributeMaxDynamicSharedMemorySize, SMEM64H);
    cudaFuncSetAttribute(gemm_fp16, cudaFuncAttributeMaxDynamicSharedMemorySize, SMEM_H);
    cudaFuncSetAttribute(attn2h,    cudaFuncAttributeMaxDynamicSharedMemorySize, SMEM_H);

    const dim3 blk(256);

    compact_kernel<<<1, 256>>>(equ_mask, sns_mask, offE, offS, mtot);
    gather2<<<dim3(BSZ, 2), 256>>>(equ_enc, sns_enc, equ_mask, sns_mask, offE, offS,
                                   ee_h, es_h, rowE, rowS, u_e, u_s);

    {
        CvtArgs ca;
        ca.seg[0] = { prev_h, ph_h, BSZ * DD / 4 };
        ca.seg[1] = { W2e,  wcat_h,                       HH * DD / 4 };
        ca.seg[2] = { W2s,  wcat_h + (size_t)HH * DD,     HH * DD / 4 };
        ca.seg[3] = { w_hh, wcat_h + (size_t)2 * HH * DD, G3D * DD / 4 };
        ca.seg[4] = { Wc,   wc_h,  HH * YC / 4 };
        ca.seg[5] = { w_ih, wih_h, G3D * HH / 4 };
        ca.seg[6] = { W1e,  w1e_h, HH * HH / 4 };
        ca.seg[7] = { W1s,  w1s_h, HH * HH / 4 };
        const int maxb = (G3D * DD / 4 + 255) / 256;
        cvt_all<<<dim3(maxb, 8), blk>>>(ca);
    }

    gemm_h64<<<dim3(NCAT / 128, BSZ / 64), blk, SMEM64H>>>(
        ph_h, wcat_h, nullptr, dtgh, nullptr, BSZ, NCAT, DD);

    plan_kernel<<<BSZ, 256>>>(prev_h, plan_W, plan_b, plan, out_plan);

    attn2h<<<dim3(BSZ, 2), blk, SMEM_H>>>(
        ee_h, es_h, w1e_h, w1s_h, dtgh, vte, vts, rowE, rowS, mtot, u_e, u_s);

    // softmax + context from the gathered fp16 rows (contiguous, half traffic)
    softmax_ctx2<<<dim3(BSZ, 2), blk>>>(u_e, u_s, ee_h, es_h, offE, offS, ctx_e, ctx_s);

    combine_kernel<<<(BSZ * YC) / 256, blk>>>(prev_y, plan, ctx_e, ctx_s, yc_h);

    gemm_h64<<<dim3(HH / 128, BSZ / 64), blk, SMEM64H>>>(
        yc_h, wc_h, bc, nullptr, x_h, BSZ, HH, YC);
    gemm_h64<<<dim3(G3D / 128, BSZ / 64), blk, SMEM64H>>>(
        x_h, wih_h, b_ih, gx, nullptr, BSZ, G3D, HH);

    gru_kernel<<<(BSZ * DD) / 256, blk>>>(gx, dtgh + 2 * HH, b_hh, prev_h, out_hid, hn_h);

    // dec_output — Wout GEMM with m-fastest grid (B n-tile L2 reuse)
    gemm_fp16<<<dim3(BSZ / 128, VV / 128), blk, SMEM_H>>>(
        hn_h, Wout, bout, out_dec, BSZ, VV, DD);
}